// round 16
// baseline (speedup 1.0000x reference)
#include <cuda_runtime.h>
#include <cuda_fp16.h>

#define N_NODES 100000
#define N_EDGES 1600000
#define NFEAT   128
#define NHID    64
#define CAP     64          // padded bucket capacity per row (max degree ~45)

typedef unsigned long long u64;

// ---- scratch (__device__ globals: no runtime allocation) -------------------
__device__ __half             g_support[N_NODES * NHID];     // 12.8 MB (fp16)
__device__ int                g_cnt[N_NODES];                 // insertion cursor == degree
__device__ unsigned long long g_edges[N_NODES * CAP];         // 51.2 MB padded buckets
__device__ unsigned short     g_mask[N_NODES * 4];            // 800 KB dropout keep-bits

// ---------------------------------------------------------------------------
// packed fp32x2 helpers (sm_103a dual-fp32 pipe; explicit PTX required)
// ---------------------------------------------------------------------------
__device__ __forceinline__ u64 pack2(float lo, float hi) {
    u64 r;
    asm("mov.b64 %0, {%1, %2};" : "=l"(r) : "f"(lo), "f"(hi));
    return r;
}
__device__ __forceinline__ void fma2(u64& d, u64 a, u64 b) {
    asm("fma.rn.f32x2 %0, %1, %2, %3;" : "=l"(d) : "l"(a), "l"(b), "l"(d));
}

// ---------------------------------------------------------------------------
// JAX partitionable threefry2x32, key (0,42), count (0, i): returns out0^out1
// ---------------------------------------------------------------------------
__device__ __forceinline__ unsigned tf_hash(unsigned i) {
    const unsigned ks0 = 0u, ks1 = 42u, ks2 = 0x1BD11BF0u;  // 0 ^ 42 ^ 0x1BD11BDA
    unsigned x0 = ks0;        // counts_hi = 0
    unsigned x1 = i + ks1;    // counts_lo = i
#define TFR(r) { x0 += x1; x1 = __funnelshift_l(x1, x1, (r)); x1 ^= x0; }
    TFR(13) TFR(15) TFR(26) TFR(6)   x0 += ks1; x1 += ks2 + 1u;
    TFR(17) TFR(29) TFR(16) TFR(24)  x0 += ks2; x1 += ks0 + 2u;
    TFR(13) TFR(15) TFR(26) TFR(6)   x0 += ks0; x1 += ks1 + 3u;
    TFR(17) TFR(29) TFR(16) TFR(24)  x0 += ks1; x1 += ks2 + 4u;
    TFR(13) TFR(15) TFR(26) TFR(6)   x0 += ks2; x1 += ks0 + 5u;
#undef TFR
    return x0 ^ x1;
}

// ---------------------------------------------------------------------------
// Bucket build + dropout-mask generation (R14-proven, unchanged).
// ---------------------------------------------------------------------------
__global__ __launch_bounds__(256) void build_kernel(const int*   __restrict__ erow,
                                                    const int*   __restrict__ ecol,
                                                    const float* __restrict__ ev) {
    int t = blockIdx.x * 256 + threadIdx.x;
    int base = t * 4;
    if (base >= N_EDGES) return;   // N_EDGES % 4 == 0: active threads fully in-bounds
    int4   r4 = *reinterpret_cast<const int4*>(erow + base);
    int4   c4 = *reinterpret_cast<const int4*>(ecol + base);
    float4 v4 = *reinterpret_cast<const float4*>(ev + base);

    // ---- dropout mask quarter-word (ALU; hides under the latency above) ----
    {
        unsigned ebase = (unsigned)t * 16u;   // == (t>>2)*64 + (t&3)*16
        unsigned m = 0;
#pragma unroll 4
        for (int k = 0; k < 16; k++)
            m |= ((~tf_hash(ebase + k)) >> 31) << k;   // keep=1 iff bit31==0
        g_mask[t] = (unsigned short)m;
    }

    int p0 = atomicAdd(&g_cnt[r4.x], 1);
    int p1 = atomicAdd(&g_cnt[r4.y], 1);
    int p2 = atomicAdd(&g_cnt[r4.z], 1);
    int p3 = atomicAdd(&g_cnt[r4.w], 1);

    if (p0 < CAP)
        g_edges[r4.x * CAP + p0] =
            ((unsigned long long)__float_as_uint(v4.x) << 32) | (unsigned)c4.x;
    if (p1 < CAP)
        g_edges[r4.y * CAP + p1] =
            ((unsigned long long)__float_as_uint(v4.y) << 32) | (unsigned)c4.y;
    if (p2 < CAP)
        g_edges[r4.z * CAP + p2] =
            ((unsigned long long)__float_as_uint(v4.z) << 32) | (unsigned)c4.z;
    if (p3 < CAP)
        g_edges[r4.w * CAP + p3] =
            ((unsigned long long)__float_as_uint(v4.w) << 32) | (unsigned)c4.w;
}

// ---------------------------------------------------------------------------
// GEMM: support[100000,64] = x[100000,128] @ W[128,64]; fp32 math via f32x2,
// fp16 store. Delta vs R15: Xs stride 36, A read as float4 over k -> LDS
// instrs per thread 1280 -> 512 (k-accumulation order unchanged: bitwise same).
// Stride-36 float4 loads: quarter-warp banks lane*4 mod 32 -> conflict-free.
// ---------------------------------------------------------------------------
__global__ __launch_bounds__(256, 2) void gemm_kernel(const float* __restrict__ x,
                                                      const float* __restrict__ W) {
    __shared__ float Xs[256][36];   // 36 KB, float4-aligned rows
    __shared__ float Ws[32][64];    //  8 KB  (total 44 KB < 48 KB)
    const int tid  = threadIdx.x;
    const int lane = tid & 31;
    const int tx   = tid >> 5;
    const int bm   = blockIdx.x * 256;

    u64 acc2[8][4];                 // 8 rows x 4 packed f32x2 (n-pairs)
#pragma unroll
    for (int j = 0; j < 8; j++)
#pragma unroll
        for (int q = 0; q < 4; q++) acc2[j][q] = 0ull;

    for (int kc = 0; kc < 4; kc++) {
#pragma unroll
        for (int i = 0; i < 8; i++) {
            int fi  = tid + i * 256;
            int row = fi >> 3;
            int kq  = fi & 7;
            int grow = bm + row;
            float4 v = make_float4(0.f, 0.f, 0.f, 0.f);
            if (grow < N_NODES)
                v = reinterpret_cast<const float4*>(x)[grow * 32 + kc * 8 + kq];
            reinterpret_cast<float4*>(&Xs[row][0])[kq] = v;
        }
#pragma unroll
        for (int i = 0; i < 2; i++) {
            int fi = tid + i * 256;
            int kk = fi >> 4;
            int nq = fi & 15;
            reinterpret_cast<float4*>(&Ws[kk][nq * 4])[0] =
                reinterpret_cast<const float4*>(W)[(kc * 32 + kk) * 16 + nq];
        }
        __syncthreads();

#pragma unroll
        for (int kg = 0; kg < 8; kg++) {        // 8 groups of 4 k
            ulonglong2 bq[4][2];
#pragma unroll
            for (int kk = 0; kk < 4; kk++) {
                bq[kk][0] = *reinterpret_cast<const ulonglong2*>(&Ws[kg * 4 + kk][tx * 8]);
                bq[kk][1] = *reinterpret_cast<const ulonglong2*>(&Ws[kg * 4 + kk][tx * 8 + 4]);
            }
#pragma unroll
            for (int j = 0; j < 8; j++) {
                float4 a4 = reinterpret_cast<const float4*>(&Xs[lane + 32 * j][0])[kg];
                u64 a0 = pack2(a4.x, a4.x);
                u64 a1 = pack2(a4.y, a4.y);
                u64 a2p = pack2(a4.z, a4.z);
                u64 a3 = pack2(a4.w, a4.w);
                fma2(acc2[j][0], a0, bq[0][0].x); fma2(acc2[j][1], a0, bq[0][0].y);
                fma2(acc2[j][2], a0, bq[0][1].x); fma2(acc2[j][3], a0, bq[0][1].y);
                fma2(acc2[j][0], a1, bq[1][0].x); fma2(acc2[j][1], a1, bq[1][0].y);
                fma2(acc2[j][2], a1, bq[1][1].x); fma2(acc2[j][3], a1, bq[1][1].y);
                fma2(acc2[j][0], a2p, bq[2][0].x); fma2(acc2[j][1], a2p, bq[2][0].y);
                fma2(acc2[j][2], a2p, bq[2][1].x); fma2(acc2[j][3], a2p, bq[2][1].y);
                fma2(acc2[j][0], a3, bq[3][0].x); fma2(acc2[j][1], a3, bq[3][0].y);
                fma2(acc2[j][2], a3, bq[3][1].x); fma2(acc2[j][3], a3, bq[3][1].y);
            }
        }
        __syncthreads();
    }

#pragma unroll
    for (int j = 0; j < 8; j++) {
        int r = bm + lane + 32 * j;
        if (r < N_NODES) {
            __half2 h[4];
#pragma unroll
            for (int q = 0; q < 4; q++) {
                float2 f = *reinterpret_cast<float2*>(&acc2[j][q]);
                h[q] = __floats2half2_rn(f.x, f.y);
            }
            reinterpret_cast<uint4*>(&g_support[r * 64 + tx * 8])[0] =
                *reinterpret_cast<uint4*>(h);
        }
    }
}

// ---------------------------------------------------------------------------
// Dummy: places reduce_kernel at kernel-launch position 4 for ncu capture.
// ---------------------------------------------------------------------------
__global__ void dummy_kernel() {}

// ---------------------------------------------------------------------------
// Gather-reduce + fused epilogue (R14/R15-proven, unchanged).
// ---------------------------------------------------------------------------
__global__ __launch_bounds__(256) void reduce_kernel(float* __restrict__ out,
                                                     const float* __restrict__ bias) {
    int lane = threadIdx.x & 31;
    int wid  = threadIdx.x >> 5;
    int row  = blockIdx.x * 8 + wid;          // grid 12500 -> exact

    int deg = g_cnt[row];
    if (deg > CAP) deg = CAP;
    const unsigned long long* ebase = g_edges + (size_t)row * CAP;

    unsigned long long mword =
        reinterpret_cast<const unsigned long long*>(g_mask)[row];

    const __half2* sup = reinterpret_cast<const __half2*>(g_support);
    float ax = 0.f, ay = 0.f;

    int nb = deg < 32 ? deg : 32;
    unsigned long long ew_l = 0;
    if (lane < nb) ew_l = ebase[lane];        // fetch only live slots
#pragma unroll 4
    for (int j = 0; j < nb; j++) {
        unsigned long long ew = __shfl_sync(0xFFFFFFFFu, ew_l, j);
        unsigned c = (unsigned)ew;
        float    v = __uint_as_float((unsigned)(ew >> 32));
        float2 s = __half22float2(sup[c * 32u + lane]);
        ax += v * s.x;
        ay += v * s.y;
    }
    if (deg > 32) {   // rare tail (P ~ 1e-4 of rows)
        int nb2 = deg - 32;
        unsigned long long ew_h = 0;
        if (lane < nb2) ew_h = ebase[32 + lane];
#pragma unroll 4
        for (int j = 0; j < nb2; j++) {
            unsigned long long ew = __shfl_sync(0xFFFFFFFFu, ew_h, j);
            unsigned c = (unsigned)ew;
            float    v = __uint_as_float((unsigned)(ew >> 32));
            float2 s = __half22float2(sup[c * 32u + lane]);
            ax += v * s.x;
            ay += v * s.y;
        }
    }

    float2 bv = reinterpret_cast<const float2*>(bias)[lane];
    float h0 = ax + bv.x, h1 = ay + bv.y;
    h0 = h0 > 0.f ? 2.f * h0 : 0.f;
    h1 = h1 > 0.f ? 2.f * h1 : 0.f;

    float2 o;
    o.x = ((mword >> (2 * lane))     & 1ull) ? h0 : 0.f;
    o.y = ((mword >> (2 * lane + 1)) & 1ull) ? h1 : 0.f;
    reinterpret_cast<float2*>(out)[(unsigned)row * 32u + lane] = o;
}

// ---------------------------------------------------------------------------
extern "C" void kernel_launch(void* const* d_in, const int* in_sizes, int n_in,
                              void* d_out, int out_size) {
    const float* x    = (const float*)d_in[0];
    const int*   erow = (const int*)  d_in[1];
    const int*   ecol = (const int*)  d_in[2];
    const float* ev   = (const float*)d_in[3];
    const float* W    = (const float*)d_in[4];
    const float* b    = (const float*)d_in[5];
    float* out = (float*)d_out;

    void* cnt_ptr = nullptr;
    cudaGetSymbolAddress(&cnt_ptr, g_cnt);
    cudaMemsetAsync(cnt_ptr, 0, N_NODES * sizeof(int), 0);

    build_kernel<<<1563, 256>>>(erow, ecol, ev);   // kernel #1
    gemm_kernel <<<391, 256>>>(x, W);              // kernel #2
    dummy_kernel<<<1, 1>>>();                      // kernel #3
    reduce_kernel<<<12500, 256>>>(out, b);         // kernel #4  <- ncu capture
}

// round 17
// speedup vs baseline: 1.1118x; 1.1118x over previous
#include <cuda_runtime.h>
#include <cuda_fp16.h>

#define N_NODES 100000
#define N_EDGES 1600000
#define NFEAT   128
#define NHID    64
#define CAP     64          // padded bucket capacity per row (max degree ~45)

typedef unsigned long long u64;

// dynamic smem layout (floats): per buffer Xs 256*36=9216 + Ws 32*64=2048
#define XS_F   9216
#define BUF_F  11264
#define GEMM_SMEM_BYTES (2 * BUF_F * 4)   // 90112 B

// ---- scratch (__device__ globals: no runtime allocation) -------------------
__device__ __half             g_support[N_NODES * NHID];     // 12.8 MB (fp16)
__device__ int                g_cnt[N_NODES];                 // insertion cursor == degree
__device__ unsigned long long g_edges[N_NODES * CAP];         // 51.2 MB padded buckets
__device__ unsigned short     g_mask[N_NODES * 4];            // 800 KB dropout keep-bits

// ---------------------------------------------------------------------------
// packed fp32x2 helpers (sm_103a dual-fp32 pipe; explicit PTX required)
// ---------------------------------------------------------------------------
__device__ __forceinline__ u64 pack2(float lo, float hi) {
    u64 r;
    asm("mov.b64 %0, {%1, %2};" : "=l"(r) : "f"(lo), "f"(hi));
    return r;
}
__device__ __forceinline__ void fma2(u64& d, u64 a, u64 b) {
    asm("fma.rn.f32x2 %0, %1, %2, %3;" : "=l"(d) : "l"(a), "l"(b), "l"(d));
}

// cp.async 16B global->shared, zero-fill when pred false
__device__ __forceinline__ void cp16(void* dst_smem, const void* src, bool pred) {
    unsigned sa = (unsigned)__cvta_generic_to_shared(dst_smem);
    int sz = pred ? 16 : 0;
    asm volatile("cp.async.cg.shared.global [%0], [%1], 16, %2;"
                 :: "r"(sa), "l"(src), "r"(sz));
}
#define CP_COMMIT() asm volatile("cp.async.commit_group;")
#define CP_WAIT1()  asm volatile("cp.async.wait_group 1;")
#define CP_WAIT0()  asm volatile("cp.async.wait_group 0;")

// ---------------------------------------------------------------------------
// JAX partitionable threefry2x32, key (0,42), count (0, i): returns out0^out1
// ---------------------------------------------------------------------------
__device__ __forceinline__ unsigned tf_hash(unsigned i) {
    const unsigned ks0 = 0u, ks1 = 42u, ks2 = 0x1BD11BF0u;  // 0 ^ 42 ^ 0x1BD11BDA
    unsigned x0 = ks0;        // counts_hi = 0
    unsigned x1 = i + ks1;    // counts_lo = i
#define TFR(r) { x0 += x1; x1 = __funnelshift_l(x1, x1, (r)); x1 ^= x0; }
    TFR(13) TFR(15) TFR(26) TFR(6)   x0 += ks1; x1 += ks2 + 1u;
    TFR(17) TFR(29) TFR(16) TFR(24)  x0 += ks2; x1 += ks0 + 2u;
    TFR(13) TFR(15) TFR(26) TFR(6)   x0 += ks0; x1 += ks1 + 3u;
    TFR(17) TFR(29) TFR(16) TFR(24)  x0 += ks1; x1 += ks2 + 4u;
    TFR(13) TFR(15) TFR(26) TFR(6)   x0 += ks2; x1 += ks0 + 5u;
#undef TFR
    return x0 ^ x1;
}

// ---------------------------------------------------------------------------
// Bucket build + dropout-mask generation (R14-proven, unchanged).
// ---------------------------------------------------------------------------
__global__ __launch_bounds__(256) void build_kernel(const int*   __restrict__ erow,
                                                    const int*   __restrict__ ecol,
                                                    const float* __restrict__ ev) {
    int t = blockIdx.x * 256 + threadIdx.x;
    int base = t * 4;
    if (base >= N_EDGES) return;   // N_EDGES % 4 == 0: active threads fully in-bounds
    int4   r4 = *reinterpret_cast<const int4*>(erow + base);
    int4   c4 = *reinterpret_cast<const int4*>(ecol + base);
    float4 v4 = *reinterpret_cast<const float4*>(ev + base);

    // ---- dropout mask quarter-word (ALU; hides under the latency above) ----
    {
        unsigned ebase = (unsigned)t * 16u;   // == (t>>2)*64 + (t&3)*16
        unsigned m = 0;
#pragma unroll 4
        for (int k = 0; k < 16; k++)
            m |= ((~tf_hash(ebase + k)) >> 31) << k;   // keep=1 iff bit31==0
        g_mask[t] = (unsigned short)m;
    }

    int p0 = atomicAdd(&g_cnt[r4.x], 1);
    int p1 = atomicAdd(&g_cnt[r4.y], 1);
    int p2 = atomicAdd(&g_cnt[r4.z], 1);
    int p3 = atomicAdd(&g_cnt[r4.w], 1);

    if (p0 < CAP)
        g_edges[r4.x * CAP + p0] =
            ((unsigned long long)__float_as_uint(v4.x) << 32) | (unsigned)c4.x;
    if (p1 < CAP)
        g_edges[r4.y * CAP + p1] =
            ((unsigned long long)__float_as_uint(v4.y) << 32) | (unsigned)c4.y;
    if (p2 < CAP)
        g_edges[r4.z * CAP + p2] =
            ((unsigned long long)__float_as_uint(v4.z) << 32) | (unsigned)c4.z;
    if (p3 < CAP)
        g_edges[r4.w * CAP + p3] =
            ((unsigned long long)__float_as_uint(v4.w) << 32) | (unsigned)c4.w;
}

// ---------------------------------------------------------------------------
// GEMM: support = x @ W, fp32 math (f32x2), fp16 store.
// Delta vs R16: cp.async DOUBLE-BUFFERED k-chunks (2 x 44KB dynamic smem).
// Chunk kc+1 streams in while chunk kc computes: DRAM latency hidden.
// Accumulation order over k unchanged -> bitwise-identical output.
// ---------------------------------------------------------------------------
__global__ __launch_bounds__(256, 2) void gemm_kernel(const float* __restrict__ x,
                                                      const float* __restrict__ W) {
    extern __shared__ float smem_dyn[];
    const int tid  = threadIdx.x;
    const int lane = tid & 31;
    const int tx   = tid >> 5;
    const int bm   = blockIdx.x * 256;

    // issue all cp.async loads for chunk kc into buffer b
    auto issue_chunk = [&](int kc, int b) {
        float* Xb = smem_dyn + b * BUF_F;
        float* Wb = Xb + XS_F;
#pragma unroll
        for (int i = 0; i < 8; i++) {
            int fi  = tid + i * 256;
            int row = fi >> 3;
            int kq  = fi & 7;
            int grow = bm + row;
            cp16(Xb + row * 36 + kq * 4,
                 x + ((size_t)grow * 32 + kc * 8 + kq) * 4,
                 grow < N_NODES);
        }
#pragma unroll
        for (int i = 0; i < 2; i++) {
            int fi = tid + i * 256;
            int kk = fi >> 4;
            int nq = fi & 15;
            cp16(Wb + kk * 64 + nq * 4,
                 W + ((size_t)(kc * 32 + kk) * 16 + nq) * 4,
                 true);
        }
        CP_COMMIT();
    };

    u64 acc2[8][4];                 // 8 rows x 4 packed f32x2 (n-pairs)
#pragma unroll
    for (int j = 0; j < 8; j++)
#pragma unroll
        for (int q = 0; q < 4; q++) acc2[j][q] = 0ull;

    issue_chunk(0, 0);
    issue_chunk(1, 1);

    for (int kc = 0; kc < 4; kc++) {
        if (kc == 3) { CP_WAIT0(); } else { CP_WAIT1(); }
        __syncthreads();            // all threads' copies for this buffer done

        const float* Xb = smem_dyn + (kc & 1) * BUF_F;
        const float* Wb = Xb + XS_F;

#pragma unroll
        for (int kg = 0; kg < 8; kg++) {        // 8 groups of 4 k
            ulonglong2 bq[4][2];
#pragma unroll
            for (int kk = 0; kk < 4; kk++) {
                bq[kk][0] = *reinterpret_cast<const ulonglong2*>(&Wb[(kg * 4 + kk) * 64 + tx * 8]);
                bq[kk][1] = *reinterpret_cast<const ulonglong2*>(&Wb[(kg * 4 + kk) * 64 + tx * 8 + 4]);
            }
#pragma unroll
            for (int j = 0; j < 8; j++) {
                float4 a4 = reinterpret_cast<const float4*>(&Xb[(lane + 32 * j) * 36])[kg];
                u64 a0 = pack2(a4.x, a4.x);
                u64 a1 = pack2(a4.y, a4.y);
                u64 a2p = pack2(a4.z, a4.z);
                u64 a3 = pack2(a4.w, a4.w);
                fma2(acc2[j][0], a0, bq[0][0].x); fma2(acc2[j][1], a0, bq[0][0].y);
                fma2(acc2[j][2], a0, bq[0][1].x); fma2(acc2[j][3], a0, bq[0][1].y);
                fma2(acc2[j][0], a1, bq[1][0].x); fma2(acc2[j][1], a1, bq[1][0].y);
                fma2(acc2[j][2], a1, bq[1][1].x); fma2(acc2[j][3], a1, bq[1][1].y);
                fma2(acc2[j][0], a2p, bq[2][0].x); fma2(acc2[j][1], a2p, bq[2][0].y);
                fma2(acc2[j][2], a2p, bq[2][1].x); fma2(acc2[j][3], a2p, bq[2][1].y);
                fma2(acc2[j][0], a3, bq[3][0].x); fma2(acc2[j][1], a3, bq[3][0].y);
                fma2(acc2[j][2], a3, bq[3][1].x); fma2(acc2[j][3], a3, bq[3][1].y);
            }
        }
        __syncthreads();            // compute done before buffer reuse
        if (kc + 2 < 4) issue_chunk(kc + 2, kc & 1);
    }

#pragma unroll
    for (int j = 0; j < 8; j++) {
        int r = bm + lane + 32 * j;
        if (r < N_NODES) {
            __half2 h[4];
#pragma unroll
            for (int q = 0; q < 4; q++) {
                float2 f = *reinterpret_cast<float2*>(&acc2[j][q]);
                h[q] = __floats2half2_rn(f.x, f.y);
            }
            reinterpret_cast<uint4*>(&g_support[r * 64 + tx * 8])[0] =
                *reinterpret_cast<uint4*>(h);
        }
    }
}

// ---------------------------------------------------------------------------
// Gather-reduce + fused epilogue (R14/R15-proven, unchanged).
// ---------------------------------------------------------------------------
__global__ __launch_bounds__(256) void reduce_kernel(float* __restrict__ out,
                                                     const float* __restrict__ bias) {
    int lane = threadIdx.x & 31;
    int wid  = threadIdx.x >> 5;
    int row  = blockIdx.x * 8 + wid;          // grid 12500 -> exact

    int deg = g_cnt[row];
    if (deg > CAP) deg = CAP;
    const unsigned long long* ebase = g_edges + (size_t)row * CAP;

    unsigned long long mword =
        reinterpret_cast<const unsigned long long*>(g_mask)[row];

    const __half2* sup = reinterpret_cast<const __half2*>(g_support);
    float ax = 0.f, ay = 0.f;

    int nb = deg < 32 ? deg : 32;
    unsigned long long ew_l = 0;
    if (lane < nb) ew_l = ebase[lane];        // fetch only live slots
#pragma unroll 4
    for (int j = 0; j < nb; j++) {
        unsigned long long ew = __shfl_sync(0xFFFFFFFFu, ew_l, j);
        unsigned c = (unsigned)ew;
        float    v = __uint_as_float((unsigned)(ew >> 32));
        float2 s = __half22float2(sup[c * 32u + lane]);
        ax += v * s.x;
        ay += v * s.y;
    }
    if (deg > 32) {   // rare tail (P ~ 1e-4 of rows)
        int nb2 = deg - 32;
        unsigned long long ew_h = 0;
        if (lane < nb2) ew_h = ebase[32 + lane];
#pragma unroll 4
        for (int j = 0; j < nb2; j++) {
            unsigned long long ew = __shfl_sync(0xFFFFFFFFu, ew_h, j);
            unsigned c = (unsigned)ew;
            float    v = __uint_as_float((unsigned)(ew >> 32));
            float2 s = __half22float2(sup[c * 32u + lane]);
            ax += v * s.x;
            ay += v * s.y;
        }
    }

    float2 bv = reinterpret_cast<const float2*>(bias)[lane];
    float h0 = ax + bv.x, h1 = ay + bv.y;
    h0 = h0 > 0.f ? 2.f * h0 : 0.f;
    h1 = h1 > 0.f ? 2.f * h1 : 0.f;

    float2 o;
    o.x = ((mword >> (2 * lane))     & 1ull) ? h0 : 0.f;
    o.y = ((mword >> (2 * lane + 1)) & 1ull) ? h1 : 0.f;
    reinterpret_cast<float2*>(out)[(unsigned)row * 32u + lane] = o;
}

// ---------------------------------------------------------------------------
extern "C" void kernel_launch(void* const* d_in, const int* in_sizes, int n_in,
                              void* d_out, int out_size) {
    const float* x    = (const float*)d_in[0];
    const int*   erow = (const int*)  d_in[1];
    const int*   ecol = (const int*)  d_in[2];
    const float* ev   = (const float*)d_in[3];
    const float* W    = (const float*)d_in[4];
    const float* b    = (const float*)d_in[5];
    float* out = (float*)d_out;

    // idempotent attribute set (not a stream op; capture-safe)
    cudaFuncSetAttribute(gemm_kernel,
                         cudaFuncAttributeMaxDynamicSharedMemorySize,
                         GEMM_SMEM_BYTES);

    void* cnt_ptr = nullptr;
    cudaGetSymbolAddress(&cnt_ptr, g_cnt);
    cudaMemsetAsync(cnt_ptr, 0, N_NODES * sizeof(int), 0);

    build_kernel<<<1563, 256>>>(erow, ecol, ev);
    gemm_kernel <<<391, 256, GEMM_SMEM_BYTES>>>(x, W);
    reduce_kernel<<<12500, 256>>>(out, b);
}